// round 15
// baseline (speedup 1.0000x reference)
#include <cuda_runtime.h>
#include <cuda_fp16.h>
#include <math.h>
#include <stdint.h>

// ---------------------------------------------------------------------------
// Vit_Spatial_Map (sm_103 PTX target => legacy mma.sync path).
// FP16 mma.sync m16n8k16, fp32 accumulate. 3 kernel launches.
// B=8, Np=1024, DIM=256, HEADS=4, DH=64, patch_dim=4096, M=8192.
//   emb  = patches @ W_embed^T + b_embed + pos   (+ fused wqavg & q-partials)
//   k    = sigmoid(q @ Wk^T) — smem-staged prelude of the kv GEMM
//   kv   = (emb @ Wv^T) * k
//   out  = fold(kv @ Wout^T + b_out)
// All GEMMs: BM=64 x BN=128 x BK=32, 256 thr, 2 CTAs/SM.
// ---------------------------------------------------------------------------

static __device__ float g_emb[8192 * 256];
static __device__ float g_kv[8192 * 256];
static __device__ float g_qp4[4 * 32 * 1024];   // [quarter][bh][n] partial q

enum { MODE_EMBED = 0, MODE_KV = 1, MODE_OUT = 2 };

__device__ __forceinline__ uint32_t pack_h2(float x, float y) {
    const __half2 h = __floats2half2_rn(x, y);
    return *reinterpret_cast<const uint32_t*>(&h);
}
__device__ __forceinline__ void mma_f16(float* c, const uint32_t* a, const uint32_t* b) {
    asm volatile(
        "mma.sync.aligned.m16n8k16.row.col.f32.f16.f16.f32 "
        "{%0,%1,%2,%3}, {%4,%5,%6,%7}, {%8,%9}, {%0,%1,%2,%3};"
        : "+f"(c[0]), "+f"(c[1]), "+f"(c[2]), "+f"(c[3])
        : "r"(a[0]), "r"(a[1]), "r"(a[2]), "r"(a[3]), "r"(b[0]), "r"(b[1]));
}

// C(M x N) = A(M x K) * B(N x K)^T. BM=64, BN=128, BK=32, 256 threads.
// Warp grid 4(m) x 2(n); warp tile 16 x 64; acc 32 regs -> 2 CTAs/SM.
// Wx param: MODE_EMBED -> Wq (fused row-mean), MODE_KV -> Wk (fused sigmoid-k).
template <int MODE, int K>
__global__ __launch_bounds__(256, 2) void gemm64(
    const float* __restrict__ Ap, const float* __restrict__ Bp,
    float* __restrict__ Cp, const float* __restrict__ bias,
    const float* __restrict__ pos, const float* __restrict__ Wx)
{
    __shared__ __align__(16) uint32_t As[2][64 * 16];
    __shared__ __align__(16) uint32_t Bs[2][128 * 16];
    __shared__ float ksm[128];                    // KV: [head_local*64 + n_local]
    __shared__ __align__(16) float qsm[2 * 1024]; // KV: summed q, 2 heads
    __shared__ float wqs[4 * 128];                // EMBED: wqavg cols of this CTA

    const int tid   = threadIdx.x;
    const int mBase = blockIdx.y * 64;
    const int nBase = blockIdx.x * 128;

    const int warp = tid >> 5;
    const int lane = tid & 31;
    const int g    = lane >> 2;
    const int tg   = lane & 3;
    const int mw   = (warp & 3) * 16;
    const int nw   = (warp >> 2) * 64;

    const float* A = (MODE == MODE_EMBED) ? Ap : (MODE == MODE_KV ? g_emb : g_kv);

    // ---- EMBED prologue: wqavg for this CTA's 128 columns (bit-identical) --
    if (MODE == MODE_EMBED) {
#pragma unroll
        for (int i = 0; i < 2; i++) {
            const int e   = tid + 256 * i;        // 0..511
            const int h   = e >> 7;
            const int col = nBase + (e & 127);
            float ssum = 0.0f;
#pragma unroll 8
            for (int d = 0; d < 64; d++)
                ssum += __ldg(&Wx[(size_t)(h * 64 + d) * 256 + col]);
            wqs[e] = ssum * (1.0f / 64.0f);
        }
    }

    // ---- KV prelude: k = sigmoid(q . Wk-row), q staged in smem -------------
    if (MODE == MODE_KV) {
        const int bn = mBase >> 10;
        const int n0 = mBase & 1023;
        const int h0 = nBase >> 6;

        // cooperative: sum 4 q-partials into qsm for both heads (8KB)
        float4* qsm4 = reinterpret_cast<float4*>(qsm);
#pragma unroll
        for (int i = 0; i < 2; i++) {
            const int e  = tid + 256 * i;         // 0..511 float4 slots
            const int hh = e >> 8;
            const int j4 = e & 255;
            const size_t qoff = (size_t)(bn * 4 + h0 + hh) * 1024;
            const float4 a = __ldg(reinterpret_cast<const float4*>(g_qp4 + 0 * 32768 + qoff) + j4);
            const float4 b = __ldg(reinterpret_cast<const float4*>(g_qp4 + 1 * 32768 + qoff) + j4);
            const float4 c = __ldg(reinterpret_cast<const float4*>(g_qp4 + 2 * 32768 + qoff) + j4);
            const float4 d = __ldg(reinterpret_cast<const float4*>(g_qp4 + 3 * 32768 + qoff) + j4);
            qsm4[e] = make_float4(a.x + b.x + c.x + d.x, a.y + b.y + c.y + d.y,
                                  a.z + b.z + c.z + d.z, a.w + b.w + c.w + d.w);
        }
        __syncthreads();

        // warp w: Wk rows n_local = w*8 .. w*8+7, dotted against BOTH heads
        const float* wk0 = Wx + (size_t)(n0 + warp * 8) * 1024;
        float s[8][2];
#pragma unroll
        for (int r = 0; r < 8; r++) { s[r][0] = 0.0f; s[r][1] = 0.0f; }
#pragma unroll
        for (int j = 0; j < 8; j++) {
            const int idx = j * 32 + lane;
            const float4 q0 = reinterpret_cast<const float4*>(qsm)[idx];
            const float4 q1 = reinterpret_cast<const float4*>(qsm)[256 + idx];
#pragma unroll
            for (int r = 0; r < 8; r++) {
                const float4 w = __ldg(reinterpret_cast<const float4*>(
                    wk0 + (size_t)r * 1024) + idx);
                s[r][0] += q0.x * w.x + q0.y * w.y + q0.z * w.z + q0.w * w.w;
                s[r][1] += q1.x * w.x + q1.y * w.y + q1.z * w.z + q1.w * w.w;
            }
        }
#pragma unroll
        for (int r = 0; r < 8; r++)
#pragma unroll
            for (int hh = 0; hh < 2; hh++) {
#pragma unroll
                for (int o = 16; o > 0; o >>= 1)
                    s[r][hh] += __shfl_xor_sync(0xFFFFFFFFu, s[r][hh], o);
                if (lane == 0)
                    ksm[hh * 64 + warp * 8 + r] = 1.0f / (1.0f + expf(-s[r][hh]));
            }
    }

    float acc[8][4];
#pragma unroll
    for (int j = 0; j < 8; j++)
#pragma unroll
        for (int l = 0; l < 4; l++) acc[j][l] = 0.0f;

    float4 av[2], bv[4];

    auto load_tile = [&](int kt) {
        const int kbase = kt * 32;
#pragma unroll
        for (int i = 0; i < 2; i++) {
            const int f   = tid + 256 * i;
            const int row = f >> 3;
            const int k4  = f & 7;
            const int ka  = kbase + k4 * 4;
            if (MODE == MODE_EMBED) {
                const int c  = ka >> 6;
                const int kh = (ka >> 3) & 7;
                const int kw = ka & 7;
                const int m  = mBase + row;
                const int bn = m >> 10, n = m & 1023;
                const int ph = n >> 5, pw = n & 31;
                const size_t idx =
                    ((((size_t)bn * 64 + c) * 256) + (size_t)(ph * 8 + kh)) * 256
                    + (size_t)(pw * 8 + kw);
                av[i] = *reinterpret_cast<const float4*>(A + idx);
            } else {
                av[i] = *reinterpret_cast<const float4*>(
                    A + (size_t)(mBase + row) * K + ka);
            }
        }
#pragma unroll
        for (int i = 0; i < 4; i++) {
            const int f   = tid + 256 * i;
            const int row = f >> 3;
            const int k4  = f & 7;
            bv[i] = *reinterpret_cast<const float4*>(
                Bp + (size_t)(nBase + row) * K + kbase + k4 * 4);
        }
    };

    auto store_tile = [&](int s) {
#pragma unroll
        for (int i = 0; i < 2; i++) {
            const int f   = tid + 256 * i;
            const int row = f >> 3;
            const int k4  = f & 7;
            const int wo  = (k4 * 2) ^ ((row & 7) * 2);
            *reinterpret_cast<uint2*>(&As[s][row * 16 + wo]) =
                make_uint2(pack_h2(av[i].x, av[i].y), pack_h2(av[i].z, av[i].w));
        }
#pragma unroll
        for (int i = 0; i < 4; i++) {
            const int f   = tid + 256 * i;
            const int row = f >> 3;
            const int k4  = f & 7;
            const int wo  = (k4 * 2) ^ ((row & 7) * 2);
            *reinterpret_cast<uint2*>(&Bs[s][row * 16 + wo]) =
                make_uint2(pack_h2(bv[i].x, bv[i].y), pack_h2(bv[i].z, bv[i].w));
        }
    };

    auto compute_tile = [&](int s) {
        const int sw = g * 2;
#pragma unroll
        for (int ks = 0; ks < 2; ks++) {
            const int w0 = (ks * 8 + tg) ^ sw;
            const int w2 = (ks * 8 + tg + 4) ^ sw;
            uint32_t a[4], b[8][2];
            {
                const uint32_t* R0 = &As[s][(mw + g) * 16];
                const uint32_t* R8 = R0 + 8 * 16;
                a[0] = R0[w0];  a[1] = R8[w0];
                a[2] = R0[w2];  a[3] = R8[w2];
            }
#pragma unroll
            for (int nt = 0; nt < 8; nt++) {
                const uint32_t* Rn = &Bs[s][(nw + nt * 8 + g) * 16];
                b[nt][0] = Rn[w0];  b[nt][1] = Rn[w2];
            }
#pragma unroll
            for (int nt = 0; nt < 8; nt++)
                mma_f16(acc[nt], a, b[nt]);
        }
    };

    constexpr int NT = K / 32;
    load_tile(0);
    store_tile(0);
    __syncthreads();   // publishes ksm (KV) / wqs (EMBED) too

    for (int kt = 0; kt < NT; kt++) {
        const int s = kt & 1;
        if (kt + 1 < NT) load_tile(kt + 1);
        compute_tile(s);
        if (kt + 1 < NT) store_tile(1 - s);
        __syncthreads();
    }

    // ---------------- epilogue ----------------
    const int qtr = (nBase + nw) >> 6;   // 64-col quarter index (EMBED)
#pragma unroll
    for (int half = 0; half < 2; half++) {
        const int m  = mBase + mw + g + half * 8;
        const int bn = m >> 10, n = m & 1023;
        float kf;
        if (MODE == MODE_KV)
            kf = ksm[(nw >> 6) * 64 + (m & 63)];
        float qs[4] = {0.f, 0.f, 0.f, 0.f};
#pragma unroll
        for (int nt = 0; nt < 8; nt++) {
            const int col = nBase + nw + nt * 8 + tg * 2;
            float vx = acc[nt][half * 2 + 0];
            float vy = acc[nt][half * 2 + 1];

            if (MODE == MODE_EMBED) {
                const float2 bb = *reinterpret_cast<const float2*>(bias + col);
                const float2 pr = *reinterpret_cast<const float2*>(
                    pos + (size_t)n * 256 + col);
                vx += bb.x + pr.x;
                vy += bb.y + pr.y;
                *reinterpret_cast<float2*>(&g_emb[(size_t)m * 256 + col]) =
                    make_float2(vx, vy);
                const int lc = nw + nt * 8 + tg * 2;   // 0..127 within CTA
#pragma unroll
                for (int h = 0; h < 4; h++) {
                    const float2 wv = *reinterpret_cast<const float2*>(
                        &wqs[h * 128 + lc]);
                    qs[h] += vx * wv.x + vy * wv.y;
                }
            } else if (MODE == MODE_KV) {
                vx *= kf; vy *= kf;
                *reinterpret_cast<float2*>(&g_kv[(size_t)m * 256 + col]) =
                    make_float2(vx, vy);
            } else {
                const float2 bb = *reinterpret_cast<const float2*>(bias + col);
                vx += bb.x;
                vy += bb.y;
                const int ph = n >> 5, pw = n & 31;
                const int c  = col >> 6;
                const int kh = (col >> 3) & 7;
                const int kw = col & 7;
                const size_t idx =
                    ((((size_t)bn * 64 + c) * 256) + (size_t)(ph * 8 + kh)) * 256
                    + (size_t)(pw * 8 + kw);
                *reinterpret_cast<float2*>(Cp + idx) = make_float2(vx, vy);
            }
        }
        if (MODE == MODE_EMBED) {
            // reduce over the tg quad -> 64-col partial q for this row
#pragma unroll
            for (int h = 0; h < 4; h++) {
                qs[h] += __shfl_xor_sync(0xFFFFFFFFu, qs[h], 1);
                qs[h] += __shfl_xor_sync(0xFFFFFFFFu, qs[h], 2);
            }
            if (tg == 0) {
#pragma unroll
                for (int h = 0; h < 4; h++)
                    g_qp4[qtr * 32768 + (bn * 4 + h) * 1024 + n] = qs[h];
            }
        }
    }
}

extern "C" void kernel_launch(void* const* d_in, const int* in_sizes, int n_in,
                              void* d_out, int out_size)
{
    const float* x    = (const float*)d_in[0];
    const float* Wemb = (const float*)d_in[1];
    const float* bemb = (const float*)d_in[2];
    const float* pos  = (const float*)d_in[3];
    const float* Wq   = (const float*)d_in[4];
    const float* Wk   = (const float*)d_in[5];
    const float* Wv   = (const float*)d_in[6];
    const float* Wout = (const float*)d_in[7];
    const float* bout = (const float*)d_in[8];
    float* out = (float*)d_out;

    gemm64<MODE_EMBED, 4096><<<dim3(2, 128), 256>>>(
        x, Wemb, nullptr, bemb, pos, Wq);
    gemm64<MODE_KV, 256><<<dim3(2, 128), 256>>>(
        nullptr, Wv, nullptr, nullptr, nullptr, Wk);
    gemm64<MODE_OUT, 256><<<dim3(32, 128), 256>>>(
        nullptr, Wout, out, bout, nullptr, nullptr);
}

// round 16
// speedup vs baseline: 1.0220x; 1.0220x over previous
#include <cuda_runtime.h>
#include <cuda_fp16.h>
#include <math.h>
#include <stdint.h>

// ---------------------------------------------------------------------------
// Vit_Spatial_Map (sm_103 PTX target => legacy mma.sync path).
// FP16 mma.sync m16n8k16, fp32 accumulate. 4 kernel launches.
// B=8, Np=1024, DIM=256, HEADS=4, DH=64, patch_dim=4096, M=8192.
//   emb  = patches @ W_embed^T + b_embed + pos   (+ fused q-partials)
//   k    = sigmoid(q @ Wk^T) — smem-staged prelude of the kv GEMM
//   kv   = (emb @ Wv^T) * k
//   out  = fold(kv @ Wout^T + b_out)
// All GEMMs: BM=64 x BN=128 x BK=32, 256 thr, 2 CTAs/SM.
// ---------------------------------------------------------------------------

static __device__ float g_emb[8192 * 256];
static __device__ float g_kv[8192 * 256];
static __device__ float g_wqavg[4 * 256];
static __device__ float g_qp4[4 * 32 * 1024];   // [quarter][bh][n] partial q

enum { MODE_EMBED = 0, MODE_KV = 1, MODE_OUT = 2 };

__device__ __forceinline__ uint32_t pack_h2(float x, float y) {
    const __half2 h = __floats2half2_rn(x, y);
    return *reinterpret_cast<const uint32_t*>(&h);
}
__device__ __forceinline__ void mma_f16(float* c, const uint32_t* a, const uint32_t* b) {
    asm volatile(
        "mma.sync.aligned.m16n8k16.row.col.f32.f16.f16.f32 "
        "{%0,%1,%2,%3}, {%4,%5,%6,%7}, {%8,%9}, {%0,%1,%2,%3};"
        : "+f"(c[0]), "+f"(c[1]), "+f"(c[2]), "+f"(c[3])
        : "r"(a[0]), "r"(a[1]), "r"(a[2]), "r"(a[3]), "r"(b[0]), "r"(b[1]));
}

// C(M x N) = A(M x K) * B(N x K)^T. BM=64, BN=128, BK=32, 256 threads.
// Warp grid 4(m) x 2(n); warp tile 16 x 64; acc 32 regs -> 2 CTAs/SM.
// Wx param: MODE_KV -> Wk (fused sigmoid-k prelude).
template <int MODE, int K>
__global__ __launch_bounds__(256, 2) void gemm64(
    const float* __restrict__ Ap, const float* __restrict__ Bp,
    float* __restrict__ Cp, const float* __restrict__ bias,
    const float* __restrict__ pos, const float* __restrict__ Wx)
{
    __shared__ __align__(16) uint32_t As[2][64 * 16];
    __shared__ __align__(16) uint32_t Bs[2][128 * 16];
    __shared__ float ksm[128];                    // KV: [head_local*64 + n_local]
    __shared__ __align__(16) float qsm[2 * 1024]; // KV: summed q, 2 heads
    __shared__ float wqs[4 * 128];                // EMBED: wqavg cols of this CTA

    const int tid   = threadIdx.x;
    const int mBase = blockIdx.y * 64;
    const int nBase = blockIdx.x * 128;

    const int warp = tid >> 5;
    const int lane = tid & 31;
    const int g    = lane >> 2;
    const int tg   = lane & 3;
    const int mw   = (warp & 3) * 16;
    const int nw   = (warp >> 2) * 64;

    const float* A = (MODE == MODE_EMBED) ? Ap : (MODE == MODE_KV ? g_emb : g_kv);

    // EMBED: stage precomputed wqavg columns (2KB) + per-thread gather bases.
    size_t aBase0 = 0, aBase1 = 0;
    if (MODE == MODE_EMBED) {
#pragma unroll
        for (int i = 0; i < 2; i++) {
            const int e = tid + 256 * i;          // 0..511
            wqs[e] = g_wqavg[(e >> 7) * 256 + nBase + (e & 127)];
        }
        // per-thread m-dependent gather base: idx = base + c*65536 + kh*256 + kw
#pragma unroll
        for (int i = 0; i < 2; i++) {
            const int row = (tid + 256 * i) >> 3;
            const int m   = mBase + row;
            const int bn  = m >> 10, n = m & 1023;
            const int ph  = n >> 5,  pw = n & 31;
            const size_t b =
                ((size_t)bn * 64) * 65536 + (size_t)(ph * 8) * 256 + (size_t)(pw * 8);
            if (i == 0) aBase0 = b; else aBase1 = b;
        }
    }

    // ---- KV prelude: k = sigmoid(q . Wk-row), q staged in smem -------------
    if (MODE == MODE_KV) {
        const int bn = mBase >> 10;
        const int n0 = mBase & 1023;
        const int h0 = nBase >> 6;

        float4* qsm4 = reinterpret_cast<float4*>(qsm);
#pragma unroll
        for (int i = 0; i < 2; i++) {
            const int e  = tid + 256 * i;         // 0..511 float4 slots
            const int hh = e >> 8;
            const int j4 = e & 255;
            const size_t qoff = (size_t)(bn * 4 + h0 + hh) * 1024;
            const float4 a = __ldg(reinterpret_cast<const float4*>(g_qp4 + 0 * 32768 + qoff) + j4);
            const float4 b = __ldg(reinterpret_cast<const float4*>(g_qp4 + 1 * 32768 + qoff) + j4);
            const float4 c = __ldg(reinterpret_cast<const float4*>(g_qp4 + 2 * 32768 + qoff) + j4);
            const float4 d = __ldg(reinterpret_cast<const float4*>(g_qp4 + 3 * 32768 + qoff) + j4);
            qsm4[e] = make_float4(a.x + b.x + c.x + d.x, a.y + b.y + c.y + d.y,
                                  a.z + b.z + c.z + d.z, a.w + b.w + c.w + d.w);
        }
        __syncthreads();

        const float* wk0 = Wx + (size_t)(n0 + warp * 8) * 1024;
        float s[8][2];
#pragma unroll
        for (int r = 0; r < 8; r++) { s[r][0] = 0.0f; s[r][1] = 0.0f; }
#pragma unroll
        for (int j = 0; j < 8; j++) {
            const int idx = j * 32 + lane;
            const float4 q0 = reinterpret_cast<const float4*>(qsm)[idx];
            const float4 q1 = reinterpret_cast<const float4*>(qsm)[256 + idx];
#pragma unroll
            for (int r = 0; r < 8; r++) {
                const float4 w = __ldg(reinterpret_cast<const float4*>(
                    wk0 + (size_t)r * 1024) + idx);
                s[r][0] += q0.x * w.x + q0.y * w.y + q0.z * w.z + q0.w * w.w;
                s[r][1] += q1.x * w.x + q1.y * w.y + q1.z * w.z + q1.w * w.w;
            }
        }
#pragma unroll
        for (int r = 0; r < 8; r++)
#pragma unroll
            for (int hh = 0; hh < 2; hh++) {
#pragma unroll
                for (int o = 16; o > 0; o >>= 1)
                    s[r][hh] += __shfl_xor_sync(0xFFFFFFFFu, s[r][hh], o);
                if (lane == 0)
                    ksm[hh * 64 + warp * 8 + r] = 1.0f / (1.0f + expf(-s[r][hh]));
            }
    }

    float acc[8][4];
#pragma unroll
    for (int j = 0; j < 8; j++)
#pragma unroll
        for (int l = 0; l < 4; l++) acc[j][l] = 0.0f;

    float4 av[2], bv[4];

    auto load_tile = [&](int kt) {
        const int kbase = kt * 32;
#pragma unroll
        for (int i = 0; i < 2; i++) {
            const int f  = tid + 256 * i;
            const int k4 = f & 7;
            const int ka = kbase + k4 * 4;
            if (MODE == MODE_EMBED) {
                // idx = baseM + c*65536 + kh*256 + kw   (3 shift/mask + 2 mad)
                const size_t idx = (i == 0 ? aBase0 : aBase1)
                    + (size_t)((ka >> 6) << 16) + (size_t)(((ka >> 3) & 7) << 8)
                    + (size_t)(ka & 7);
                av[i] = *reinterpret_cast<const float4*>(A + idx);
            } else {
                const int row = f >> 3;
                av[i] = *reinterpret_cast<const float4*>(
                    A + (size_t)(mBase + row) * K + ka);
            }
        }
#pragma unroll
        for (int i = 0; i < 4; i++) {
            const int f   = tid + 256 * i;
            const int row = f >> 3;
            const int k4  = f & 7;
            bv[i] = *reinterpret_cast<const float4*>(
                Bp + (size_t)(nBase + row) * K + kbase + k4 * 4);
        }
    };

    auto store_tile = [&](int s) {
#pragma unroll
        for (int i = 0; i < 2; i++) {
            const int f   = tid + 256 * i;
            const int row = f >> 3;
            const int k4  = f & 7;
            const int wo  = (k4 * 2) ^ ((row & 7) * 2);
            *reinterpret_cast<uint2*>(&As[s][row * 16 + wo]) =
                make_uint2(pack_h2(av[i].x, av[i].y), pack_h2(av[i].z, av[i].w));
        }
#pragma unroll
        for (int i = 0; i < 4; i++) {
            const int f   = tid + 256 * i;
            const int row = f >> 3;
            const int k4  = f & 7;
            const int wo  = (k4 * 2) ^ ((row & 7) * 2);
            *reinterpret_cast<uint2*>(&Bs[s][row * 16 + wo]) =
                make_uint2(pack_h2(bv[i].x, bv[i].y), pack_h2(bv[i].z, bv[i].w));
        }
    };

    auto compute_tile = [&](int s) {
        const int sw = g * 2;
#pragma unroll
        for (int ks = 0; ks < 2; ks++) {
            const int w0 = (ks * 8 + tg) ^ sw;
            const int w2 = (ks * 8 + tg + 4) ^ sw;
            uint32_t a[4], b[8][2];
            {
                const uint32_t* R0 = &As[s][(mw + g) * 16];
                const uint32_t* R8 = R0 + 8 * 16;
                a[0] = R0[w0];  a[1] = R8[w0];
                a[2] = R0[w2];  a[3] = R8[w2];
            }
#pragma unroll
            for (int nt = 0; nt < 8; nt++) {
                const uint32_t* Rn = &Bs[s][(nw + nt * 8 + g) * 16];
                b[nt][0] = Rn[w0];  b[nt][1] = Rn[w2];
            }
#pragma unroll
            for (int nt = 0; nt < 8; nt++)
                mma_f16(acc[nt], a, b[nt]);
        }
    };

    constexpr int NT = K / 32;
    load_tile(0);
    store_tile(0);
    __syncthreads();   // publishes ksm (KV) / wqs (EMBED) too

    for (int kt = 0; kt < NT; kt++) {
        const int s = kt & 1;
        if (kt + 1 < NT) load_tile(kt + 1);
        compute_tile(s);
        if (kt + 1 < NT) store_tile(1 - s);
        __syncthreads();
    }

    // ---------------- epilogue ----------------
    const int qtr = (nBase + nw) >> 6;   // 64-col quarter index (EMBED)
#pragma unroll
    for (int half = 0; half < 2; half++) {
        const int m  = mBase + mw + g + half * 8;
        const int bn = m >> 10, n = m & 1023;
        float kf;
        if (MODE == MODE_KV)
            kf = ksm[(nw >> 6) * 64 + (m & 63)];
        float qs[4] = {0.f, 0.f, 0.f, 0.f};
#pragma unroll
        for (int nt = 0; nt < 8; nt++) {
            const int col = nBase + nw + nt * 8 + tg * 2;
            float vx = acc[nt][half * 2 + 0];
            float vy = acc[nt][half * 2 + 1];

            if (MODE == MODE_EMBED) {
                const float2 bb = *reinterpret_cast<const float2*>(bias + col);
                const float2 pr = *reinterpret_cast<const float2*>(
                    pos + (size_t)n * 256 + col);
                vx += bb.x + pr.x;
                vy += bb.y + pr.y;
                *reinterpret_cast<float2*>(&g_emb[(size_t)m * 256 + col]) =
                    make_float2(vx, vy);
                const int lc = nw + nt * 8 + tg * 2;   // 0..127 within CTA
#pragma unroll
                for (int h = 0; h < 4; h++) {
                    const float2 wv = *reinterpret_cast<const float2*>(
                        &wqs[h * 128 + lc]);
                    qs[h] += vx * wv.x + vy * wv.y;
                }
            } else if (MODE == MODE_KV) {
                vx *= kf; vy *= kf;
                *reinterpret_cast<float2*>(&g_kv[(size_t)m * 256 + col]) =
                    make_float2(vx, vy);
            } else {
                const float2 bb = *reinterpret_cast<const float2*>(bias + col);
                vx += bb.x;
                vy += bb.y;
                const int ph = n >> 5, pw = n & 31;
                const int c  = col >> 6;
                const int kh = (col >> 3) & 7;
                const int kw = col & 7;
                const size_t idx =
                    ((((size_t)bn * 64 + c) * 256) + (size_t)(ph * 8 + kh)) * 256
                    + (size_t)(pw * 8 + kw);
                *reinterpret_cast<float2*>(Cp + idx) = make_float2(vx, vy);
            }
        }
        if (MODE == MODE_EMBED) {
            // reduce over the tg quad -> 64-col partial q for this row
#pragma unroll
            for (int h = 0; h < 4; h++) {
                qs[h] += __shfl_xor_sync(0xFFFFFFFFu, qs[h], 1);
                qs[h] += __shfl_xor_sync(0xFFFFFFFFu, qs[h], 2);
            }
            if (tg == 0) {
#pragma unroll
                for (int h = 0; h < 4; h++)
                    g_qp4[qtr * 32768 + (bn * 4 + h) * 1024 + n] = qs[h];
            }
        }
    }
}

// Wq_avg[h][j] = mean over d of Wq[h*64+d][j]  (runs BEFORE embed GEMM)
__global__ void k_wqavg(const float* __restrict__ Wq)
{
    const int h = blockIdx.x, j = threadIdx.x;
    float s = 0.0f;
#pragma unroll 8
    for (int d = 0; d < 64; d++) s += Wq[(size_t)(h * 64 + d) * 256 + j];
    g_wqavg[h * 256 + j] = s * (1.0f / 64.0f);
}

extern "C" void kernel_launch(void* const* d_in, const int* in_sizes, int n_in,
                              void* d_out, int out_size)
{
    const float* x    = (const float*)d_in[0];
    const float* Wemb = (const float*)d_in[1];
    const float* bemb = (const float*)d_in[2];
    const float* pos  = (const float*)d_in[3];
    const float* Wq   = (const float*)d_in[4];
    const float* Wk   = (const float*)d_in[5];
    const float* Wv   = (const float*)d_in[6];
    const float* Wout = (const float*)d_in[7];
    const float* bout = (const float*)d_in[8];
    float* out = (float*)d_out;

    k_wqavg<<<4, 256>>>(Wq);
    gemm64<MODE_EMBED, 4096><<<dim3(2, 128), 256>>>(
        x, Wemb, nullptr, bemb, pos, nullptr);
    gemm64<MODE_KV, 256><<<dim3(2, 128), 256>>>(
        nullptr, Wv, nullptr, nullptr, nullptr, Wk);
    gemm64<MODE_OUT, 256><<<dim3(32, 128), 256>>>(
        nullptr, Wout, out, bout, nullptr, nullptr);
}